// round 14
// baseline (speedup 1.0000x reference)
#include <cuda_runtime.h>
#include <cstdint>

#define B_     16
#define P_     784
#define D_     10000
#define WPITCH 320
#define NROW_  1040        // 784 pw rows + 256 vw rows
#define NXB_   25          // extra k_pack blocks for x quantize
#define NGW    10          // wordgroups of 32 words
#define NSP    16          // p splits of 49

// ---- device scratch ----
__device__ unsigned g_pack[NROW_ * WPITCH];       // [row][word] row-major (1.33 MB)
__device__ unsigned g_idxr[16 * 16 * 16];         // level bytes [ch][b][64B] (16 KB)
__device__ unsigned g_part[NSP * 6 * 16 * WPITCH];// 6-plane partials (1.97 MB)

__device__ __forceinline__ unsigned maj3(unsigned a, unsigned b, unsigned c) {
    return (a & b) | (a & c) | (b & c);   // single LOP3
}

// ============ K1: pack sign bits (row-major), quantize x ============
// Word W: bit l <-> column 128*(W>>2) + 4*l + (W&3)
__global__ __launch_bounds__(512)
void k_pack(const float* __restrict__ x,
            const float* __restrict__ pw,
            const float* __restrict__ vw)
{
    int bid = blockIdx.x;
    if (bid < NROW_) {
        const float* src = (bid < P_) ? (pw + (size_t)bid * D_)
                                      : (vw + (size_t)(bid - P_) * D_);
        int wid = threadIdx.x >> 5, lane = threadIdx.x & 31;

        float4 f[5];                        // MLP=5 per thread
        #pragma unroll
        for (int k = 0; k < 5; k++) {
            int g   = wid + k * 16;
            int col = g * 128 + lane * 4;
            bool ok = (g < 79) && (col + 3 < D_);
            f[k] = ok ? *reinterpret_cast<const float4*>(src + col)
                      : make_float4(1.f, 1.f, 1.f, 1.f);
        }
        #pragma unroll
        for (int k = 0; k < 5; k++) {
            int g = wid + k * 16;
            if (g < 79) {                   // warp-uniform
                unsigned m0 = __ballot_sync(0xffffffffu, f[k].x < 0.f);
                unsigned m1 = __ballot_sync(0xffffffffu, f[k].y < 0.f);
                unsigned m2 = __ballot_sync(0xffffffffu, f[k].z < 0.f);
                unsigned m3 = __ballot_sync(0xffffffffu, f[k].w < 0.f);
                if (lane < 4) {
                    unsigned mm = (lane == 0) ? m0 : (lane == 1) ? m1
                                 : (lane == 2) ? m2 : m3;
                    g_pack[bid * WPITCH + g * 4 + lane] = mm;
                }
            }
        }
    } else {
        int i = (bid - NROW_) * 512 + threadIdx.x;
        if (i < B_ * P_) {
            int b = i / P_, p = i - b * P_;
            int ch = p / 49, j = p - ch * 49;
            int q = __float2int_rn(x[i] * 255.0f);   // matches jnp.round (RN-even)
            q = max(0, min(255, q));
            reinterpret_cast<unsigned char*>(g_idxr)[((ch * 16 + b) << 6) + j] =
                (unsigned char)q;
        }
    }
}

// ============ K2: warp-uniform-level accumulate (ZERO bank conflicts) ============
// Block = (g of 32 words, sp of 49 p). Warp = b, lane = word.
__global__ __launch_bounds__(512, 2)
void k_acc()
{
    __shared__ unsigned vw_s[256 * 32];   // [lev][word] bank=lane  32 KB
    __shared__ unsigned pw_s[49 * 32];    // [p][word]   bank=lane  6.3 KB

    const int g    = blockIdx.x >> 4;
    const int sp   = blockIdx.x & 15;
    const int t    = threadIdx.x;
    const int b    = t >> 5;              // warp = batch
    const int lane = t & 31;              // lane = word

    // ---- coalesced tile fills ----
    for (int i = t; i < 256 * 32; i += 512)
        vw_s[i] = g_pack[(size_t)(P_ + (i >> 5)) * WPITCH + g * 32 + (i & 31)];
    for (int i = t; i < 49 * 32; i += 512)
        pw_s[i] = g_pack[(size_t)(sp * 49 + (i >> 5)) * WPITCH + g * 32 + (i & 31)];

    // ---- 49 level bytes for (sp, b) -> registers (warp-uniform broadcast) ----
    unsigned u[13];
    {
        const uint4* ib = reinterpret_cast<const uint4*>(g_idxr + ((sp * 16 + b) << 4));
        uint4 a0 = ib[0], a1 = ib[1], a2 = ib[2];
        u[0]=a0.x; u[1]=a0.y; u[2]=a0.z;  u[3]=a0.w;
        u[4]=a1.x; u[5]=a1.y; u[6]=a1.z;  u[7]=a1.w;
        u[8]=a2.x; u[9]=a2.y; u[10]=a2.z; u[11]=a2.w;
        u[12] = g_idxr[((sp * 16 + b) << 4) + 12];
    }
    __syncthreads();

    // ---- 49 positions = 7 CSA groups of 7; every LDS is bank=lane ----
    unsigned cc0 = 0, cc1 = 0, cc2 = 0, cc3 = 0, cc4 = 0, cc5 = 0;
    #pragma unroll
    for (int gg = 0; gg < 7; gg++) {
        unsigned s[7];
        #pragma unroll
        for (int jj = 0; jj < 7; jj++) {
            int j = gg * 7 + jj;                       // compile-time constant
            unsigned lev = (u[j >> 2] >> ((j & 3) * 8)) & 255u;  // warp-uniform
            s[jj] = vw_s[lev * 32 + lane] ^ pw_s[j * 32 + lane];
        }
        unsigned t1s = s[0] ^ s[1] ^ s[2], t1c = maj3(s[0], s[1], s[2]);
        unsigned t2s = s[3] ^ s[4] ^ s[5], t2c = maj3(s[3], s[4], s[5]);
        unsigned q0  = t1s ^ t2s ^ s[6],   t3c = maj3(t1s, t2s, s[6]);
        unsigned q1  = t1c ^ t2c ^ t3c;
        unsigned q2  = maj3(t1c, t2c, t3c);
        unsigned cr = cc0 & q0;            cc0 ^= q0;
        unsigned n1 = maj3(cc1, q1, cr);   cc1 = cc1 ^ q1 ^ cr;  cr = n1;
        unsigned n2 = maj3(cc2, q2, cr);   cc2 = cc2 ^ q2 ^ cr;  cr = n2;
        unsigned n3 = cc3 & cr;            cc3 ^= cr;            cr = n3;
        unsigned n4 = cc4 & cr;            cc4 ^= cr;            cr = n4;
        cc5 ^= cr;                                               // max 49 < 64
    }

    // ---- coalesced 6-plane partial write ----
    {
        size_t base = (size_t)((sp * 6) * 16 + b) * WPITCH + g * 32 + lane;
        g_part[base]               = cc0;
        g_part[base + 16u*WPITCH]  = cc1;
        g_part[base + 32u*WPITCH]  = cc2;
        g_part[base + 48u*WPITCH]  = cc3;
        g_part[base + 64u*WPITCH]  = cc4;
        g_part[base + 80u*WPITCH]  = cc5;
    }
}

// ============ K3: combine 16 splits -> sign, store ============
// Block = (g, b-half). Thread = (b, w).
__global__ __launch_bounds__(256)
void k_fin(float* __restrict__ out)
{
    __shared__ unsigned br_s[8][32];      // [b-local][word]

    const int g  = blockIdx.x >> 1;
    const int h  = blockIdx.x & 1;
    const int t  = threadIdx.x;
    const int bl = t >> 5;                // local b
    const int b  = h * 8 + bl;
    const int w  = t & 31;

    unsigned P0=0,P1=0,P2=0,P3=0,P4=0,P5=0,P6=0,P7=0,P8=0,P9=0;
    #pragma unroll
    for (int sp = 0; sp < NSP; sp++) {
        size_t base = (size_t)((sp * 6) * 16 + b) * WPITCH + g * 32 + w;
        unsigned a0 = g_part[base];
        unsigned a1 = g_part[base + 16u*WPITCH];
        unsigned a2 = g_part[base + 32u*WPITCH];
        unsigned a3 = g_part[base + 48u*WPITCH];
        unsigned a4 = g_part[base + 64u*WPITCH];
        unsigned a5 = g_part[base + 80u*WPITCH];
        unsigned cr, n;
        cr = P0 & a0;           P0 ^= a0;
        n = maj3(P1, a1, cr);   P1 = P1 ^ a1 ^ cr;  cr = n;
        n = maj3(P2, a2, cr);   P2 = P2 ^ a2 ^ cr;  cr = n;
        n = maj3(P3, a3, cr);   P3 = P3 ^ a3 ^ cr;  cr = n;
        n = maj3(P4, a4, cr);   P4 = P4 ^ a4 ^ cr;  cr = n;
        n = maj3(P5, a5, cr);   P5 = P5 ^ a5 ^ cr;  cr = n;
        n = P6 & cr;  P6 ^= cr;  cr = n;
        n = P7 & cr;  P7 ^= cr;  cr = n;
        n = P8 & cr;  P8 ^= cr;  cr = n;
        P9 ^= cr;                                    // max 784 < 1024
    }
    // borrow of (cnt - 392); 392 = bits 3,7,8.  br=1 <=> cnt<392 <=> +1
    {
        unsigned br = 0;
        br = ~P0 & br;  br = ~P1 & br;  br = ~P2 & br;
        br = ~P3 | br;
        br = ~P4 & br;  br = ~P5 & br;  br = ~P6 & br;
        br = ~P7 | br;  br = ~P8 | br;
        br = ~P9 & br;
        br_s[bl][w] = br;
    }
    __syncthreads();

    // ---- coalesced sign store: group g covers cols [1024g, 1024g+1024) ----
    {
        const int l = w;                  // bit within word = column quad offset
        float* orow = out + (size_t)b * D_;
        #pragma unroll
        for (int k = 0; k < 8; k++) {     // quad = g*8 + k, words k*4..k*4+3
            int col0 = 128 * (g * 8 + k) + 4 * l;
            if (col0 + 3 < D_) {
                const unsigned* brq = &br_s[bl][k * 4];
                float4 v;
                v.x = __uint_as_float(0x3F800000u | ((((brq[0] >> l) & 1u) ^ 1u) << 31));
                v.y = __uint_as_float(0x3F800000u | ((((brq[1] >> l) & 1u) ^ 1u) << 31));
                v.z = __uint_as_float(0x3F800000u | ((((brq[2] >> l) & 1u) ^ 1u) << 31));
                v.w = __uint_as_float(0x3F800000u | ((((brq[3] >> l) & 1u) ^ 1u) << 31));
                *reinterpret_cast<float4*>(orow + col0) = v;
            }
        }
    }
}

extern "C" void kernel_launch(void* const* d_in, const int* in_sizes, int n_in,
                              void* d_out, int out_size)
{
    (void)in_sizes; (void)n_in; (void)out_size;
    const float* x  = (const float*)d_in[0];   // (16, 28, 28)
    const float* pw = (const float*)d_in[1];   // (784, 10000)
    const float* vw = (const float*)d_in[2];   // (256, 10000)
    float* out = (float*)d_out;                // (16, 10000)

    k_pack<<<NROW_ + NXB_, 512>>>(x, pw, vw);
    k_acc<<<NGW * NSP, 512>>>();
    k_fin<<<NGW * 2, 256>>>(out);
}